// round 1
// baseline (speedup 1.0000x reference)
#include <cuda_runtime.h>
#include <cstdint>
#include <cstddef>

// Problem constants
#define BB 4
#define SS 2048
#define DM 2048
#define HH 16
#define HD 128
static __device__ __constant__ float SCALEF = 0.08838834764831845f; // 1/sqrt(128)

// ---------------- scratch (device globals; no allocation allowed) ----------------
__device__ float g_Q [(size_t)BB * HH * SS * HD];   // [B,H,S,HD]   64 MB
__device__ float g_Kt[(size_t)BB * HH * HD * SS];   // [B,H,HD,S]   64 MB
__device__ float g_V [(size_t)BB * HH * SS * HD];   // [B,H,S,HD]   64 MB
__device__ float g_P [(size_t)BB * HH * SS * SS];   // [B,H,S,S]     1 GB (scores/probs)
__device__ float g_O [(size_t)BB * SS * DM];        // [B,S,D]      64 MB

// ---------------- f32x2 packed-FMA helpers (sm_103a) ----------------
__device__ __forceinline__ unsigned long long pk2(float lo, float hi) {
    unsigned long long r;
    asm("mov.b64 %0, {%1, %2};" : "=l"(r) : "f"(lo), "f"(hi));
    return r;
}
__device__ __forceinline__ float2 upk2(unsigned long long u) {
    float2 f;
    asm("mov.b64 {%0, %1}, %2;" : "=f"(f.x), "=f"(f.y) : "l"(u));
    return f;
}
__device__ __forceinline__ void fma2(unsigned long long& c, unsigned long long a, unsigned long long b) {
    asm("fma.rn.f32x2 %0, %1, %2, %0;" : "+l"(c) : "l"(a), "l"(b));
}

// ---------------- generic tiled SGEMM, 128x128x16, 256 threads, 8x8/thread ----------------
// MODE 0: C[m,n] = acc + bias[n]                       (standard, row-major C [M,N])
// MODE 1: heads:   C[((b*H+h)*S+s)*HD + d] = acc+bias  (proj -> [B,H,S,HD])
// MODE 2: heads^T: C[((b*H+h)*HD+d)*S + s] = acc+bias  (proj -> [B,H,HD,S])
// MODE 3: C[m,n] = acc * SCALE                         (scores, batched over z)
// MODE 4: C[(b*S+m)*DM + h*HD + n] = acc               (PV -> [B,S,D], z = b*H+h)
template <int MODE>
__global__ __launch_bounds__(256, 2)
void sgemm(const float* __restrict__ A, const float* __restrict__ Bm,
           const float* __restrict__ bias, float* __restrict__ C,
           int M, int N, int K, int lda, int ldb,
           size_t strideA, size_t strideB, size_t strideC)
{
    __shared__ float As[16][128];   // transposed A tile: As[k][m]
    __shared__ float Bs[16][128];   // B tile: Bs[k][n]

    A  += (size_t)blockIdx.z * strideA;
    Bm += (size_t)blockIdx.z * strideB;
    C  += (size_t)blockIdx.z * strideC;

    const int tid = threadIdx.x;
    const int tx = tid & 15;   // col group 0..15
    const int ty = tid >> 4;   // row group 0..15
    const int bm = blockIdx.y * 128;
    const int bn = blockIdx.x * 128;

    // A tile load mapping: 2 float4 per thread
    const int ar = tid >> 2;          // 0..63
    const int ac = (tid & 3) * 4;     // 0,4,8,12
    // B tile load mapping: 2 float4 per thread
    const int brow = tid >> 5;        // 0..7
    const int bcol = (tid & 31) * 4;  // 0..124

    unsigned long long acc[8][4];
    #pragma unroll
    for (int i = 0; i < 8; i++)
        #pragma unroll
        for (int j = 0; j < 4; j++) acc[i][j] = 0ull;

    for (int kt = 0; kt < K; kt += 16) {
        float4 a0 = *(const float4*)&A[(size_t)(bm + ar)      * lda + kt + ac];
        float4 a1 = *(const float4*)&A[(size_t)(bm + ar + 64) * lda + kt + ac];
        float4 b0 = *(const float4*)&Bm[(size_t)(kt + brow)     * ldb + bn + bcol];
        float4 b1 = *(const float4*)&Bm[(size_t)(kt + brow + 8) * ldb + bn + bcol];
        __syncthreads();
        As[ac + 0][ar] = a0.x;  As[ac + 1][ar] = a0.y;
        As[ac + 2][ar] = a0.z;  As[ac + 3][ar] = a0.w;
        As[ac + 0][ar + 64] = a1.x;  As[ac + 1][ar + 64] = a1.y;
        As[ac + 2][ar + 64] = a1.z;  As[ac + 3][ar + 64] = a1.w;
        *(float4*)&Bs[brow][bcol]     = b0;
        *(float4*)&Bs[brow + 8][bcol] = b1;
        __syncthreads();

        #pragma unroll
        for (int k = 0; k < 16; k++) {
            float4 af0 = *(const float4*)&As[k][ty * 4];
            float4 af1 = *(const float4*)&As[k][64 + ty * 4];
            float4 bf0 = *(const float4*)&Bs[k][tx * 4];
            float4 bf1 = *(const float4*)&Bs[k][64 + tx * 4];
            unsigned long long bl0 = pk2(bf0.x, bf0.y), bh0 = pk2(bf0.z, bf0.w);
            unsigned long long bl1 = pk2(bf1.x, bf1.y), bh1 = pk2(bf1.z, bf1.w);
            float avs[8] = {af0.x, af0.y, af0.z, af0.w, af1.x, af1.y, af1.z, af1.w};
            #pragma unroll
            for (int i = 0; i < 8; i++) {
                unsigned long long a2 = pk2(avs[i], avs[i]);
                fma2(acc[i][0], a2, bl0);
                fma2(acc[i][1], a2, bh0);
                fma2(acc[i][2], a2, bl1);
                fma2(acc[i][3], a2, bh1);
            }
        }
    }

    // ---------------- epilogue ----------------
    #pragma unroll
    for (int ig = 0; ig < 2; ig++) {
        #pragma unroll
        for (int ii = 0; ii < 4; ii++) {
            const int i = ig * 4 + ii;
            const int r = bm + ig * 64 + ty * 4 + ii;       // global row
            #pragma unroll
            for (int jg = 0; jg < 2; jg++) {
                float2 p0 = upk2(acc[i][jg * 2 + 0]);
                float2 p1 = upk2(acc[i][jg * 2 + 1]);
                float4 v = make_float4(p0.x, p0.y, p1.x, p1.y);
                const int cw = jg * 64 + tx * 4;            // col within tile
                const int c  = bn + cw;                     // global col

                if (MODE == 0) {
                    v.x += bias[c]; v.y += bias[c + 1]; v.z += bias[c + 2]; v.w += bias[c + 3];
                    *(float4*)&C[(size_t)r * N + c] = v;
                } else if (MODE == 3) {
                    v.x *= SCALEF; v.y *= SCALEF; v.z *= SCALEF; v.w *= SCALEF;
                    *(float4*)&C[(size_t)r * N + c] = v;
                } else if (MODE == 1) {
                    const int b = r >> 11, s = r & 2047;    // S = 2048
                    const int h = blockIdx.x;               // N=2048, BN=128 => head per block col
                    v.x += bias[c]; v.y += bias[c + 1]; v.z += bias[c + 2]; v.w += bias[c + 3];
                    *(float4*)&C[(((size_t)(b * HH + h)) * SS + s) * HD + cw] = v;
                } else if (MODE == 2) {
                    const int b = r >> 11, s = r & 2047;
                    const int h = blockIdx.x;
                    const size_t base = ((size_t)(b * HH + h)) * HD;
                    C[(base + cw + 0) * SS + s] = v.x + bias[c];
                    C[(base + cw + 1) * SS + s] = v.y + bias[c + 1];
                    C[(base + cw + 2) * SS + s] = v.z + bias[c + 2];
                    C[(base + cw + 3) * SS + s] = v.w + bias[c + 3];
                } else { // MODE 4
                    const int bh = blockIdx.z;
                    const int b = bh >> 4, h = bh & 15;
                    *(float4*)&C[((size_t)b * SS + r) * DM + h * HD + c] = v;
                }
            }
        }
    }
}

// ---------------- masked softmax over rows of scores ----------------
__global__ __launch_bounds__(256)
void softmax_mask(float* __restrict__ P, const int* __restrict__ mask)
{
    const int q = blockIdx.x;
    const int bh = blockIdx.y;
    const int b = bh >> 4;
    float* row = P + ((size_t)bh * SS + q) * SS;
    const int* mrow = mask + ((size_t)b * SS + q) * SS;
    const int t = threadIdx.x;

    float v[8];
    float mx = -3.0e38f;
    #pragma unroll
    for (int i = 0; i < 8; i++) {
        const int c = t + (i << 8);
        float xv = row[c];
        if (mrow[c] == 0) xv = -3.0e38f;
        v[i] = xv;
        mx = fmaxf(mx, xv);
    }
    #pragma unroll
    for (int o = 16; o; o >>= 1) mx = fmaxf(mx, __shfl_xor_sync(0xffffffffu, mx, o));
    __shared__ float smax[8];
    __shared__ float ssum[8];
    if ((t & 31) == 0) smax[t >> 5] = mx;
    __syncthreads();
    #pragma unroll
    for (int w = 0; w < 8; w++) mx = fmaxf(mx, smax[w]);

    float sum = 0.f;
    #pragma unroll
    for (int i = 0; i < 8; i++) {
        float p = __expf(v[i] - mx);
        v[i] = p;
        sum += p;
    }
    #pragma unroll
    for (int o = 16; o; o >>= 1) sum += __shfl_xor_sync(0xffffffffu, sum, o);
    if ((t & 31) == 0) ssum[t >> 5] = sum;
    __syncthreads();
    float ts = 0.f;
    #pragma unroll
    for (int w = 0; w < 8; w++) ts += ssum[w];
    const float inv = 1.0f / ts;
    #pragma unroll
    for (int i = 0; i < 8; i++) row[t + (i << 8)] = v[i] * inv;
}

// ---------------- launch ----------------
extern "C" void kernel_launch(void* const* d_in, const int* in_sizes, int n_in,
                              void* d_out, int out_size)
{
    const float* x  = (const float*)d_in[0];
    const int*   mask = (const int*)d_in[1];
    const float* Wq = (const float*)d_in[2];
    const float* bq = (const float*)d_in[3];
    const float* Wk = (const float*)d_in[4];
    const float* bk = (const float*)d_in[5];
    const float* Wv = (const float*)d_in[6];
    const float* bv = (const float*)d_in[7];
    const float* Wo = (const float*)d_in[8];
    const float* bo = (const float*)d_in[9];
    float* out = (float*)d_out;

    float *Q, *Kt, *V, *P, *O;
    cudaGetSymbolAddress((void**)&Q,  g_Q);
    cudaGetSymbolAddress((void**)&Kt, g_Kt);
    cudaGetSymbolAddress((void**)&V,  g_V);
    cudaGetSymbolAddress((void**)&P,  g_P);
    cudaGetSymbolAddress((void**)&O,  g_O);

    const dim3 thr(256);
    const int Mx = BB * SS;  // 8192

    // Projections: [8192,2048] @ [2048,2048]
    sgemm<1><<<dim3(16, 64, 1), thr>>>(x, Wq, bq, Q,  Mx, DM, DM, DM, DM, 0, 0, 0);
    sgemm<2><<<dim3(16, 64, 1), thr>>>(x, Wk, bk, Kt, Mx, DM, DM, DM, DM, 0, 0, 0);
    sgemm<1><<<dim3(16, 64, 1), thr>>>(x, Wv, bv, V,  Mx, DM, DM, DM, DM, 0, 0, 0);

    // Scores: per (b,h): [2048,128] @ [128,2048], scaled
    sgemm<3><<<dim3(16, 16, BB * HH), thr>>>(Q, Kt, nullptr, P,
        SS, SS, HD, HD, SS,
        (size_t)SS * HD, (size_t)HD * SS, (size_t)SS * SS);

    // Softmax with mask
    softmax_mask<<<dim3(SS, BB * HH), 256>>>(P, mask);

    // PV: per (b,h): [2048,2048] @ [2048,128] -> scattered into O [B,S,D]
    sgemm<4><<<dim3(1, 16, BB * HH), thr>>>(P, V, nullptr, O,
        SS, HD, SS, SS, HD,
        (size_t)SS * SS, (size_t)SS * HD, 0);

    // Output projection: [8192,2048] @ [2048,2048] + bo
    sgemm<0><<<dim3(16, 64, 1), thr>>>(O, Wo, bo, out, Mx, DM, DM, DM, DM, 0, 0, 0);
}

// round 5
// speedup vs baseline: 2.3484x; 2.3484x over previous
#include <cuda_runtime.h>
#include <cuda_bf16.h>
#include <cstdint>
#include <cstddef>

// ---------------- problem constants ----------------
#define BB 4
#define SS 2048
#define DM 2048
#define HH 16
#define HD 128
#define MX (BB*SS)   // 8192
#define SCALEF 0.08838834764831845f

// ---------------- GEMM geometry ----------------
// CTA tile 128x128, K_tile = 64 bf16, double buffered.
// SMEM per buffer: Ah(16K) Al(16K) Bh(16K) Bl(16K) = 64K; x2 = 128K.
#define KTILE 64
#define BUF_BYTES 65536
#define SMEMSZ    131072

// ---------------- scratch (device globals; no allocation allowed) ----------------
__device__ __nv_bfloat16 g_xh[(size_t)MX*DM], g_xl[(size_t)MX*DM];
__device__ __nv_bfloat16 g_Wh[4][(size_t)DM*DM], g_Wl[4][(size_t)DM*DM];   // W^T split [N][K]
__device__ __nv_bfloat16 g_Qh[(size_t)BB*HH*SS*HD], g_Ql[(size_t)BB*HH*SS*HD];
__device__ __nv_bfloat16 g_Kh[(size_t)BB*HH*SS*HD], g_Kl[(size_t)BB*HH*SS*HD];
__device__ float         g_Vf[(size_t)BB*HH*SS*HD];                         // V heads f32
__device__ __nv_bfloat16 g_Vth[(size_t)BB*HH*HD*SS], g_Vtl[(size_t)BB*HH*HD*SS]; // V^T split
__device__ float         g_Pf[(size_t)BB*HH*SS*SS];                         // scores f32 (1 GB)
__device__ __nv_bfloat16 g_Ph[(size_t)BB*HH*SS*SS], g_Pl[(size_t)BB*HH*SS*SS];
__device__ __nv_bfloat16 g_Oh[(size_t)MX*DM], g_Ol[(size_t)MX*DM];

// ---------------- PTX helpers (family-portable only: no tcgen05/TMA) ----------------
__device__ __forceinline__ uint32_t smem_u32(const void* p) {
    uint32_t a;
    asm("{ .reg .u64 t; cvta.to.shared.u64 t, %1; cvt.u32.u64 %0, t; }" : "=r"(a) : "l"(p));
    return a;
}
__device__ __forceinline__ uint32_t sw128(uint32_t b) { return b ^ ((b >> 3) & 0x70); }

__device__ __forceinline__ void cp16(uint32_t s, const void* g) {
    asm volatile("cp.async.cg.shared.global [%0], [%1], 16;" :: "r"(s), "l"(g));
}
__device__ __forceinline__ void cp_commit() { asm volatile("cp.async.commit_group;"); }
__device__ __forceinline__ void cp_wait0() { asm volatile("cp.async.wait_group 0;" ::: "memory"); }
__device__ __forceinline__ void cp_wait1() { asm volatile("cp.async.wait_group 1;" ::: "memory"); }

__device__ __forceinline__ void ldsm4(uint32_t* r, uint32_t a) {
    asm volatile("ldmatrix.sync.aligned.m8n8.x4.shared.b16 {%0,%1,%2,%3}, [%4];"
        : "=r"(r[0]), "=r"(r[1]), "=r"(r[2]), "=r"(r[3]) : "r"(a));
}
__device__ __forceinline__ void mma16816(float* c, const uint32_t* a, const uint32_t* b) {
    asm volatile("mma.sync.aligned.m16n8k16.row.col.f32.bf16.bf16.f32 "
        "{%0,%1,%2,%3}, {%4,%5,%6,%7}, {%8,%9}, {%0,%1,%2,%3};"
        : "+f"(c[0]), "+f"(c[1]), "+f"(c[2]), "+f"(c[3])
        : "r"(a[0]), "r"(a[1]), "r"(a[2]), "r"(a[3]), "r"(b[0]), "r"(b[1]));
}

// ---------------- hi/lo split helpers ----------------
__device__ __forceinline__ void split2(float x, __nv_bfloat16& h, __nv_bfloat16& l) {
    h = __float2bfloat16_rn(x);
    l = __float2bfloat16_rn(x - __bfloat162float(h));
}
// pack two (hi,lo) splits into two bf16x2 words
__device__ __forceinline__ void pack2(float x0, float x1, uint32_t& hi, uint32_t& lo) {
    __nv_bfloat16 h0, l0, h1, l1;
    split2(x0, h0, l0);
    split2(x1, h1, l1);
    hi = (uint32_t)__bfloat16_as_ushort(h0) | ((uint32_t)__bfloat16_as_ushort(h1) << 16);
    lo = (uint32_t)__bfloat16_as_ushort(l0) | ((uint32_t)__bfloat16_as_ushort(l1) << 16);
}

// ---------------- warp-MMA GEMM: C[128x128] per CTA, bf16x3 ----------------
// 8 warps = 2 (M) x 4 (N); warp tile 64x32; mma m16n8k16 row.col.
// MODE 0: f32 out + bias -> Cf[r*DM + c]                      (output projection)
// MODE 1: split out + bias -> heads [BH][S][HD]               (Q/K projections)
// MODE 2: f32 out + bias -> heads [BH][S][HD]                 (V projection)
// MODE 3: f32 out * SCALE -> Cf + z*sC, row len SS            (scores)
// MODE 4: split out -> O [B][S][DM] at h*HD                   (PV)
template <int MODE>
__global__ __launch_bounds__(256, 1)
void tgemm(const __nv_bfloat16* __restrict__ Ah, const __nv_bfloat16* __restrict__ Al,
           const __nv_bfloat16* __restrict__ Bh, const __nv_bfloat16* __restrict__ Bl,
           const float* __restrict__ bias, float* __restrict__ Cf,
           __nv_bfloat16* __restrict__ Ch, __nv_bfloat16* __restrict__ Cl,
           int K, int lda, int ldb, size_t sA, size_t sB, size_t sC)
{
    extern __shared__ __align__(1024) char smem[];
    const uint32_t sbase = smem_u32(smem);
    const int tid  = threadIdx.x;
    const int wid  = tid >> 5;
    const int lane = tid & 31;
    const int z = blockIdx.z;
    Ah += (size_t)z * sA;  Al += (size_t)z * sA;
    Bh += (size_t)z * sB;  Bl += (size_t)z * sB;
    const int bm = blockIdx.y * 128;
    const int bn = blockIdx.x * 128;

    const int mwarp = wid >> 2;     // 0..1
    const int nwarp = wid & 3;      // 0..3

    // ---- lane-constant fragment addressing (within a 16KB plane, swizzled) ----
    // A: r = mwarp*64 + mb*16 + (lane&15), col byte = ks*32 + (lane>>4)*16
    const uint32_t aRow = (uint32_t)(mwarp * 64 + (lane & 15)) * 128;
    const uint32_t kA   = (uint32_t)(lane >> 4) * 16;
    // B: n = nwarp*32 + g*16 + (lane&7) + ((lane>>4)<<3), col byte = ks*32 + ((lane>>3)&1)*16
    const uint32_t bRow = (uint32_t)(nwarp * 32 + (lane & 7) + ((lane >> 4) << 3)) * 128;
    const uint32_t kB   = (uint32_t)((lane >> 3) & 1) * 16;
    const uint32_t swx  = (uint32_t)(lane & 7) << 4;    // swizzle XOR bits (same for A and B)

    float acc[4][4][4];
    #pragma unroll
    for (int i = 0; i < 4; i++)
        #pragma unroll
        for (int j = 0; j < 4; j++)
            #pragma unroll
            for (int q = 0; q < 4; q++) acc[i][j][q] = 0.f;

    const int NT = K >> 6;   // K / 64

    auto issue = [&](int kt, int b) {
        const uint32_t bb = sbase + (uint32_t)b * BUF_BYTES;
        const int k0 = kt * KTILE;
        #pragma unroll
        for (int j = 0; j < 4; j++) {
            const int idx = tid + j * 256;   // 0..1023
            const int r   = idx >> 3;        // 0..127
            const int c16 = idx & 7;         // 0..7
            const uint32_t so = sw128((uint32_t)(r * 128 + c16 * 16));
            const size_t aoff = (size_t)(bm + r) * lda + k0 + c16 * 8;
            const size_t boff = (size_t)(bn + r) * ldb + k0 + c16 * 8;
            cp16(bb +         so, Ah + aoff);
            cp16(bb + 16384 + so, Al + aoff);
            cp16(bb + 32768 + so, Bh + boff);
            cp16(bb + 49152 + so, Bl + boff);
        }
        cp_commit();
    };

    issue(0, 0);

    for (int kt = 0; kt < NT; kt++) {
        const int b = kt & 1;
        if (kt + 1 < NT) { issue(kt + 1, b ^ 1); cp_wait1(); }
        else             { cp_wait0(); }
        __syncthreads();   // buffer b fully resident for all warps

        const uint32_t bb = sbase + (uint32_t)b * BUF_BYTES;
        #pragma unroll
        for (int ks = 0; ks < 4; ks++) {
            uint32_t AhF[4][4], AlF[4][4], BhF[4][2], BlF[4][2];
            const uint32_t colA = ((uint32_t)(ks * 32) + kA) ^ swx;
            const uint32_t colB = ((uint32_t)(ks * 32) + kB) ^ swx;
            #pragma unroll
            for (int mb = 0; mb < 4; mb++) {
                const uint32_t ad = bb + aRow + (uint32_t)mb * 2048 + colA;
                ldsm4(AhF[mb], ad);
                ldsm4(AlF[mb], ad + 16384);
            }
            #pragma unroll
            for (int g = 0; g < 2; g++) {
                uint32_t t[4];
                const uint32_t bd = bb + 32768 + bRow + (uint32_t)g * 2048 + colB;
                ldsm4(t, bd);
                BhF[2*g][0] = t[0]; BhF[2*g][1] = t[1];
                BhF[2*g+1][0] = t[2]; BhF[2*g+1][1] = t[3];
                ldsm4(t, bd + 16384);
                BlF[2*g][0] = t[0]; BlF[2*g][1] = t[1];
                BlF[2*g+1][0] = t[2]; BlF[2*g+1][1] = t[3];
            }
            // pass 0: Ah*Bh
            #pragma unroll
            for (int mb = 0; mb < 4; mb++)
                #pragma unroll
                for (int nb = 0; nb < 4; nb++)
                    mma16816(acc[mb][nb], AhF[mb], BhF[nb]);
            // pass 1: Ah*Bl
            #pragma unroll
            for (int mb = 0; mb < 4; mb++)
                #pragma unroll
                for (int nb = 0; nb < 4; nb++)
                    mma16816(acc[mb][nb], AhF[mb], BlF[nb]);
            // pass 2: Al*Bh
            #pragma unroll
            for (int mb = 0; mb < 4; mb++)
                #pragma unroll
                for (int nb = 0; nb < 4; nb++)
                    mma16816(acc[mb][nb], AlF[mb], BhF[nb]);
        }
        __syncthreads();   // all reads of buffer b done before it is refilled
    }

    // ---------------- epilogue (registers -> global) ----------------
    #pragma unroll
    for (int mb = 0; mb < 4; mb++) {
        #pragma unroll
        for (int nb = 0; nb < 4; nb++) {
            const float* a = acc[mb][nb];
            const int r0 = bm + mwarp * 64 + mb * 16 + (lane >> 2);
            const int c0 = bn + nwarp * 32 + nb * 8 + 2 * (lane & 3);
            const int cl = c0 - bn;   // col within tile

            if (MODE == 0) {
                const float b0f = bias[c0], b1f = bias[c0 + 1];
                *(float2*)&Cf[(size_t)r0 * DM + c0]       = make_float2(a[0] + b0f, a[1] + b1f);
                *(float2*)&Cf[(size_t)(r0 + 8) * DM + c0] = make_float2(a[2] + b0f, a[3] + b1f);
            } else if (MODE == 3) {
                float* C = Cf + (size_t)z * sC;
                *(float2*)&C[(size_t)r0 * SS + c0]       = make_float2(a[0] * SCALEF, a[1] * SCALEF);
                *(float2*)&C[(size_t)(r0 + 8) * SS + c0] = make_float2(a[2] * SCALEF, a[3] * SCALEF);
            } else if (MODE == 1 || MODE == 2) {
                const int bI = r0 >> 11;          // batch (tile never crosses)
                const int h  = blockIdx.x;
                const float b0f = bias[c0], b1f = bias[c0 + 1];
                const int s0 = r0 & (SS - 1), s1 = (r0 + 8) & (SS - 1);
                const size_t base0 = (((size_t)(bI * HH + h)) * SS + s0) * HD + cl;
                const size_t base1 = (((size_t)(bI * HH + h)) * SS + s1) * HD + cl;
                if (MODE == 2) {
                    *(float2*)&Cf[base0] = make_float2(a[0] + b0f, a[1] + b1f);
                    *(float2*)&Cf[base1] = make_float2(a[2] + b0f, a[3] + b1f);
                } else {
                    uint32_t hi, lo;
                    pack2(a[0] + b0f, a[1] + b1f, hi, lo);
                    *(uint32_t*)&Ch[base0] = hi; *(uint32_t*)&Cl[base0] = lo;
                    pack2(a[2] + b0f, a[3] + b1f, hi, lo);
                    *(uint32_t*)&Ch[base1] = hi; *(uint32_t*)&Cl[base1] = lo;
                }
            } else { // MODE 4
                const int bI = z >> 4, h = z & 15;
                const size_t base0 = ((size_t)bI * SS + r0) * DM + h * HD + cl;
                const size_t base1 = ((size_t)bI * SS + r0 + 8) * DM + h * HD + cl;
                uint32_t hi, lo;
                pack2(a[0], a[1], hi, lo);
                *(uint32_t*)&Ch[base0] = hi; *(uint32_t*)&Cl[base0] = lo;
                pack2(a[2], a[3], hi, lo);
                *(uint32_t*)&Ch[base1] = hi; *(uint32_t*)&Cl[base1] = lo;
            }
        }
    }
}

// ---------------- aux kernels ----------------
__global__ __launch_bounds__(256)
void split_kernel(const float* __restrict__ in, __nv_bfloat16* __restrict__ oh,
                  __nv_bfloat16* __restrict__ ol, size_t n4)
{
    size_t i = (size_t)blockIdx.x * blockDim.x + threadIdx.x;
    const size_t stride = (size_t)gridDim.x * blockDim.x;
    for (; i < n4; i += stride) {
        float4 x = ((const float4*)in)[i];
        uint32_t h0, l0, h1, l1;
        pack2(x.x, x.y, h0, l0);
        pack2(x.z, x.w, h1, l1);
        ((uint2*)oh)[i] = make_uint2(h0, h1);
        ((uint2*)ol)[i] = make_uint2(l0, l1);
    }
}

// transpose [R][C] f32 -> split bf16 [C][R]
__global__ __launch_bounds__(256)
void transpose_split(const float* __restrict__ in, __nv_bfloat16* __restrict__ oh,
                     __nv_bfloat16* __restrict__ ol, int R, int C, size_t sIn, size_t sOut)
{
    __shared__ float t[32][33];
    in += (size_t)blockIdx.z * sIn;
    oh += (size_t)blockIdx.z * sOut;
    ol += (size_t)blockIdx.z * sOut;
    const int r0 = blockIdx.y * 32, c0 = blockIdx.x * 32;
    const int tx = threadIdx.x, ty = threadIdx.y;   // (32, 8)
    #pragma unroll
    for (int i = 0; i < 4; i++)
        t[ty + i*8][tx] = in[(size_t)(r0 + ty + i*8) * C + c0 + tx];
    __syncthreads();
    #pragma unroll
    for (int i = 0; i < 4; i++) {
        float v = t[tx][ty + i*8];
        __nv_bfloat16 h, l;
        split2(v, h, l);
        const size_t o = (size_t)(c0 + ty + i*8) * R + r0 + tx;
        oh[o] = h;
        ol[o] = l;
    }
}

__global__ __launch_bounds__(256)
void softmax_mask(const float* __restrict__ P, const int* __restrict__ mask,
                  __nv_bfloat16* __restrict__ Ph, __nv_bfloat16* __restrict__ Pl)
{
    const int q = blockIdx.x;
    const int bh = blockIdx.y;
    const int b = bh >> 4;
    const float* row = P + ((size_t)bh * SS + q) * SS;
    const int* mrow = mask + ((size_t)b * SS + q) * SS;
    const size_t obase = ((size_t)bh * SS + q) * SS;
    const int t = threadIdx.x;

    float v[8];
    float mx = -3.0e38f;
    #pragma unroll
    for (int i = 0; i < 8; i++) {
        const int c = t + (i << 8);
        float xv = row[c];
        if (mrow[c] == 0) xv = -3.0e38f;
        v[i] = xv;
        mx = fmaxf(mx, xv);
    }
    #pragma unroll
    for (int o = 16; o; o >>= 1) mx = fmaxf(mx, __shfl_xor_sync(0xffffffffu, mx, o));
    __shared__ float smax[8], ssum[8];
    if ((t & 31) == 0) smax[t >> 5] = mx;
    __syncthreads();
    #pragma unroll
    for (int w = 0; w < 8; w++) mx = fmaxf(mx, smax[w]);

    float sum = 0.f;
    #pragma unroll
    for (int i = 0; i < 8; i++) { float p = __expf(v[i] - mx); v[i] = p; sum += p; }
    #pragma unroll
    for (int o = 16; o; o >>= 1) sum += __shfl_xor_sync(0xffffffffu, sum, o);
    if ((t & 31) == 0) ssum[t >> 5] = sum;
    __syncthreads();
    float ts = 0.f;
    #pragma unroll
    for (int w = 0; w < 8; w++) ts += ssum[w];
    const float inv = 1.0f / ts;
    #pragma unroll
    for (int i = 0; i < 8; i++) {
        const int c = t + (i << 8);
        __nv_bfloat16 h, l;
        split2(v[i] * inv, h, l);
        Ph[obase + c] = h;
        Pl[obase + c] = l;
    }
}

// ---------------- launch ----------------
extern "C" void kernel_launch(void* const* d_in, const int* in_sizes, int n_in,
                              void* d_out, int out_size)
{
    (void)in_sizes; (void)n_in; (void)out_size;
    const float* x    = (const float*)d_in[0];
    const int*   mask = (const int*)d_in[1];
    const float* Wq = (const float*)d_in[2];
    const float* bq = (const float*)d_in[3];
    const float* Wk = (const float*)d_in[4];
    const float* bk = (const float*)d_in[5];
    const float* Wv = (const float*)d_in[6];
    const float* bv = (const float*)d_in[7];
    const float* Wo = (const float*)d_in[8];
    const float* bo = (const float*)d_in[9];
    float* out = (float*)d_out;

    __nv_bfloat16 *xh, *xl, *Wh, *Wl, *Qh, *Ql, *Kh, *Kl, *Vth, *Vtl, *Ph, *Pl, *Oh, *Ol;
    float *Vf, *Pf;
    cudaGetSymbolAddress((void**)&xh, g_xh);   cudaGetSymbolAddress((void**)&xl, g_xl);
    cudaGetSymbolAddress((void**)&Wh, g_Wh);   cudaGetSymbolAddress((void**)&Wl, g_Wl);
    cudaGetSymbolAddress((void**)&Qh, g_Qh);   cudaGetSymbolAddress((void**)&Ql, g_Ql);
    cudaGetSymbolAddress((void**)&Kh, g_Kh);   cudaGetSymbolAddress((void**)&Kl, g_Kl);
    cudaGetSymbolAddress((void**)&Vf, g_Vf);
    cudaGetSymbolAddress((void**)&Vth, g_Vth); cudaGetSymbolAddress((void**)&Vtl, g_Vtl);
    cudaGetSymbolAddress((void**)&Pf, g_Pf);
    cudaGetSymbolAddress((void**)&Ph, g_Ph);   cudaGetSymbolAddress((void**)&Pl, g_Pl);
    cudaGetSymbolAddress((void**)&Oh, g_Oh);   cudaGetSymbolAddress((void**)&Ol, g_Ol);

    cudaFuncSetAttribute(tgemm<0>, cudaFuncAttributeMaxDynamicSharedMemorySize, SMEMSZ);
    cudaFuncSetAttribute(tgemm<1>, cudaFuncAttributeMaxDynamicSharedMemorySize, SMEMSZ);
    cudaFuncSetAttribute(tgemm<2>, cudaFuncAttributeMaxDynamicSharedMemorySize, SMEMSZ);
    cudaFuncSetAttribute(tgemm<3>, cudaFuncAttributeMaxDynamicSharedMemorySize, SMEMSZ);
    cudaFuncSetAttribute(tgemm<4>, cudaFuncAttributeMaxDynamicSharedMemorySize, SMEMSZ);

    const size_t WSZ = (size_t)DM * DM;
    const dim3 tb(32, 8);

    // split x; transpose+split weights
    split_kernel<<<8192, 256>>>(x, xh, xl, (size_t)MX * DM / 4);
    transpose_split<<<dim3(64, 64, 1), tb>>>(Wq, Wh + 0*WSZ, Wl + 0*WSZ, DM, DM, 0, 0);
    transpose_split<<<dim3(64, 64, 1), tb>>>(Wk, Wh + 1*WSZ, Wl + 1*WSZ, DM, DM, 0, 0);
    transpose_split<<<dim3(64, 64, 1), tb>>>(Wv, Wh + 2*WSZ, Wl + 2*WSZ, DM, DM, 0, 0);
    transpose_split<<<dim3(64, 64, 1), tb>>>(Wo, Wh + 3*WSZ, Wl + 3*WSZ, DM, DM, 0, 0);

    // projections: [8192,2048] @ W^T
    tgemm<1><<<dim3(16, 64, 1), 256, SMEMSZ>>>(xh, xl, Wh + 0*WSZ, Wl + 0*WSZ, bq,
        nullptr, Qh, Ql, DM, DM, DM, 0, 0, 0);
    tgemm<1><<<dim3(16, 64, 1), 256, SMEMSZ>>>(xh, xl, Wh + 1*WSZ, Wl + 1*WSZ, bk,
        nullptr, Kh, Kl, DM, DM, DM, 0, 0, 0);
    tgemm<2><<<dim3(16, 64, 1), 256, SMEMSZ>>>(xh, xl, Wh + 2*WSZ, Wl + 2*WSZ, bv,
        Vf, nullptr, nullptr, DM, DM, DM, 0, 0, 0);

    // V -> V^T split  (per (b,h): [S][HD] -> [HD][S])
    transpose_split<<<dim3(4, 64, BB * HH), tb>>>(Vf, Vth, Vtl, SS, HD,
        (size_t)SS * HD, (size_t)SS * HD);

    // scores: per (b,h) [S,HD] x [S,HD]^T
    tgemm<3><<<dim3(16, 16, BB * HH), 256, SMEMSZ>>>(Qh, Ql, Kh, Kl, nullptr,
        Pf, nullptr, nullptr, HD, HD, HD,
        (size_t)SS * HD, (size_t)SS * HD, (size_t)SS * SS);

    softmax_mask<<<dim3(SS, BB * HH), 256>>>(Pf, mask, Ph, Pl);

    // PV: per (b,h) [S,S] x V^T[HD,S] -> O scattered to [B,S,DM]
    tgemm<4><<<dim3(1, 16, BB * HH), 256, SMEMSZ>>>(Ph, Pl, Vth, Vtl, nullptr,
        nullptr, Oh, Ol, SS, SS, SS,
        (size_t)SS * SS, (size_t)HD * SS, 0);

    // output projection
    tgemm<0><<<dim3(16, 64, 1), 256, SMEMSZ>>>(Oh, Ol, Wh + 3*WSZ, Wl + 3*WSZ, bo,
        out, nullptr, nullptr, DM, DM, DM, 0, 0, 0);
}